// round 12
// baseline (speedup 1.0000x reference)
#include <cuda_runtime.h>
#include <cstdint>

#define NS 13824            // D*H*W = 24*24*24
#define NB 2                // batch
#define NC 64               // channels
#define NVOX (NB * NS)      // 27648 voxels
#define PD 26               // padded dim
#define PD2 (PD * PD)       // 676
#define P3 (PD * PD * PD)   // 17576 padded voxels per batch
#define NBORD 3752          // border voxels per batch = P3 - NS
#define NPROJ (NVOX / 64)   // 432 projection blocks
#define NZERO ((NB * NBORD * 16) / 256)   // 469 border-zero blocks

// attn smem: halo buffer (160 vox * 64 f) + p buffer (27 * 128 f)
#define HALO_F (160 * 64)                 // 10240 floats
#define PBUF_F (27 * 128)                 // 3456 floats
#define ATTN_SMEM ((HALO_F + PBUF_F) * 4) // 54784 bytes -> 4 blocks/SM

// q unpadded voxel-major [n][c] (pre-scaled by 0.25*log2e);
// k,v zero-padded [b][dp][hp][wp][c]
__device__ float g_q [NVOX * NC];
__device__ float g_kp[NB * P3 * NC];
__device__ float g_vp[NB * P3 * NC];

typedef unsigned long long u64;

__device__ __forceinline__ u64 pack2(float lo, float hi) {
    u64 r; asm("mov.b64 %0,{%1,%2};" : "=l"(r) : "f"(lo), "f"(hi)); return r;
}
__device__ __forceinline__ float2 unpack2(u64 v) {
    float2 r; asm("mov.b64 {%0,%1},%2;" : "=f"(r.x), "=f"(r.y) : "l"(v)); return r;
}
__device__ __forceinline__ u64 fma2(u64 a, u64 b, u64 c) {
    u64 d; asm("fma.rn.f32x2 %0,%1,%2,%3;" : "=l"(d) : "l"(a), "l"(b), "l"(c)); return d;
}
__device__ __forceinline__ u64 add2(u64 a, u64 b) {
    u64 d; asm("add.rn.f32x2 %0,%1,%2;" : "=l"(d) : "l"(a), "l"(b)); return d;
}
__device__ __forceinline__ float ex2(float x) {
    float r; asm("ex2.approx.ftz.f32 %0,%1;" : "=f"(r) : "f"(x)); return r;
}

// ---------------------------------------------------------------------------
// Kernel 1: QKV projection + (tail blocks) border zeroing. (unchanged)
// ---------------------------------------------------------------------------
__global__ __launch_bounds__(256) void k_proj(
    const float* __restrict__ x,
    const float* __restrict__ Wq, const float* __restrict__ bq,
    const float* __restrict__ Wk, const float* __restrict__ bk,
    const float* __restrict__ Wv, const float* __restrict__ bv)
{
    __shared__ __align__(16) float WTs[64 * 68];   // WTs[j*68 + c] = W[c][j]
    __shared__ __align__(16) float Xs[64 * 64];    // Xs[j*64 + t]

    const int tid = threadIdx.x;

    if (blockIdx.x >= NPROJ) {
        // ---- border zeroing tail blocks ----
        int idx = (blockIdx.x - NPROJ) * 256 + tid;   // [0, NB*NBORD*16)
        int t  = idx >> 4;
        int c4 = (idx & 15) * 4;
        int bb = t / NBORD;
        int r  = t % NBORD;

        int dp, hp, wp;
        if (r < 1352) {                   // faces dp = 0 / 25
            dp = (r >= 676) ? 25 : 0;
            int q = (r >= 676) ? r - 676 : r;
            hp = q / PD; wp = q % PD;
        } else if (r < 2600) {            // faces hp = 0 / 25
            int q = r - 1352;
            dp = 1 + q / 52;
            int q2 = q % 52;
            hp = (q2 >= 26) ? 25 : 0;
            wp = (q2 >= 26) ? q2 - 26 : q2;
        } else {                          // faces wp = 0 / 25
            int q = r - 2600;
            dp = 1 + q / 48;
            int q2 = q % 48;
            hp = 1 + (q2 >> 1);
            wp = (q2 & 1) ? 25 : 0;
        }

        long vox = (long)bb * P3 + dp * PD2 + hp * PD + wp;
        float4 z = make_float4(0.f, 0.f, 0.f, 0.f);
        *(float4*)&g_kp[vox * NC + c4] = z;
        *(float4*)&g_vp[vox * NC + c4] = z;
        return;
    }

    // ---- projection blocks ----
    const int lane = tid & 31;
    const int wid  = tid >> 5;
    const int tile = blockIdx.x;               // 0..431
    const int bb   = tile / (NS / 64);
    const int s0   = (tile % (NS / 64)) * 64;

    const float* xb = x + (long)bb * NC * NS + s0;

#pragma unroll
    for (int k = 0; k < 16; k++) {
        int idx = tid + k * 256;
        int j = idx >> 6, u = idx & 63;
        Xs[j * 64 + u] = xb[(long)j * NS + u];
    }

    const int c0  = (wid & 1) * 32 + (lane >> 2) * 4;
    const int tv0 = (wid >> 1) * 16 + (lane & 3) * 4;

    const int sA = s0 + tv0;
    const int d  = sA / 576, h = (sA / 24) % 24, w0 = sA % 24;
    const long nq  = (long)(bb * NS + sA) * NC + c0;
    const long npk = ((long)bb * P3 + (d + 1) * PD2 + (h + 1) * PD + (w0 + 1)) * NC + c0;

    const float* Wsrc[3] = {Wq, Wk, Wv};
    const float* bsrc[3] = {bq, bk, bv};

#pragma unroll
    for (int m = 0; m < 3; m++) {
        __syncthreads();
        const float* W = Wsrc[m];
#pragma unroll
        for (int k2 = 0; k2 < 16; k2++) {
            int idx = tid + k2 * 256;
            int c = idx >> 6, j = idx & 63;
            WTs[j * 68 + c] = W[idx];
        }
        __syncthreads();

        const float4 bv4 = *(const float4*)&bsrc[m][c0];
        u64 acc[4][2];
#pragma unroll
        for (int t = 0; t < 4; t++) {
            acc[t][0] = pack2(bv4.x, bv4.y);
            acc[t][1] = pack2(bv4.z, bv4.w);
        }

#pragma unroll 8
        for (int j = 0; j < 64; j++) {
            ulonglong2 w = *(const ulonglong2*)&WTs[j * 68 + c0];
            float4 xv = *(const float4*)&Xs[j * 64 + tv0];
            u64 xd0 = pack2(xv.x, xv.x);
            u64 xd1 = pack2(xv.y, xv.y);
            u64 xd2 = pack2(xv.z, xv.z);
            u64 xd3 = pack2(xv.w, xv.w);
            acc[0][0] = fma2(w.x, xd0, acc[0][0]);
            acc[0][1] = fma2(w.y, xd0, acc[0][1]);
            acc[1][0] = fma2(w.x, xd1, acc[1][0]);
            acc[1][1] = fma2(w.y, xd1, acc[1][1]);
            acc[2][0] = fma2(w.x, xd2, acc[2][0]);
            acc[2][1] = fma2(w.y, xd2, acc[2][1]);
            acc[3][0] = fma2(w.x, xd3, acc[3][0]);
            acc[3][1] = fma2(w.y, xd3, acc[3][1]);
        }

        if (m == 0) {
            // 2^(q'.k) == e^(0.25 * q.k)
            const float qs = 0.25f * 1.4426950408889634f;
#pragma unroll
            for (int t = 0; t < 4; t++) {
                float2 a = unpack2(acc[t][0]);
                float2 b = unpack2(acc[t][1]);
                float4 o;
                o.x = a.x * qs; o.y = a.y * qs;
                o.z = b.x * qs; o.w = b.y * qs;
                *(float4*)&g_q[nq + (long)t * NC] = o;
            }
        } else {
            float* g = (m == 1) ? g_kp : g_vp;
#pragma unroll
            for (int t = 0; t < 4; t++) {
                float2 a = unpack2(acc[t][0]);
                float2 b = unpack2(acc[t][1]);
                float4 o; o.x = a.x; o.y = a.y; o.z = b.x; o.w = b.y;
                *(float4*)&g[npk + (long)t * NC] = o;
            }
        }
    }
}

// ---------------------------------------------------------------------------
// Kernel 2: 3x3x3 local attention + residual, SMEM-staged, TWO-PHASE.
// Block = 2x2x8 voxel tile, 4x4x10 halo. ONE 40KB halo buffer is reused:
//   phase A: buffer holds k-halo; compute p = 2^(q.k) for all 27 neighbors
//            per (query, head), store p into a 13.5KB smem p-buffer.
//   phase B: overwrite buffer with v-halo; read p back (broadcast LDS.32)
//            and accumulate p*v.
// Halves smem/block vs R11 (80KB -> 53.5KB) => 4 blocks/SM, ~2x occupancy
// for the same LDS volume; math bit-identical to R11.
// Lane owns 8 channels (slot-permuted records: conflict-free LDS.128),
// lane-pair = head, ONE shfl per dot. Base-2 single-pass softmax (q
// pre-scaled by 0.25*log2e; padded halo gives 2^0=1 with zero v).
// ---------------------------------------------------------------------------
__global__ __launch_bounds__(256) void k_attn(
    const float* __restrict__ x, float* __restrict__ out)
{
    extern __shared__ __align__(16) float sm[];
    float* hal = sm;            // 160 voxels * 64 floats (k, then v)
    float* ps  = sm + HALO_F;   // p[27][128]: n*128 + grp*4 + head
    float* hs  = sm;            // reused for output staging (64*33)

    const int tid = threadIdx.x;
    const int bb = blockIdx.x / 432;
    const int r  = blockIdx.x % 432;
    const int d0 = (r / 36) * 2;          // 12 d-tiles
    const int h0 = ((r / 3) % 12) * 2;    // 12 h-tiles
    const int w0 = (r % 3) * 8;           // 3 w-tiles

    // halo origin in padded coords = (d0, h0, w0)
    const long gb = ((long)bb * P3 + d0 * PD2 + h0 * PD + w0) * NC;

    // ---- phase A: k-halo load (slot-permuted records) ----
#pragma unroll
    for (int it = 0; it < 10; it++) {
        int e = tid + it * 256;           // [0, 2560)
        int vox = e >> 4, f = e & 15;
        int slot = ((f & 1) << 3) | (f >> 1);
        int dd = vox / 40, rr2 = vox % 40, hh = rr2 / 10, ww = rr2 % 10;
        long g = gb + ((long)dd * PD2 + hh * PD + ww) * NC + f * 4;
        *(float4*)&hal[vox * 64 + slot * 4] = *(const float4*)&g_kp[g];
    }
    __syncthreads();

    const int l8  = tid & 7;             // channel slot: owns channels l8*8..+8
    const int grp = tid >> 3;            // voxel 0..31 in tile
    const int hd  = l8 >> 1;             // head of this lane-pair
    const int td = grp >> 4, th = (grp >> 3) & 1, tw = grp & 7;
    const int c0 = l8 * 8;

    // q: 8 channels = 4 f32x2 pairs
    const long qa = ((long)bb * NS + (d0 + td) * 576 + (h0 + th) * 24 + (w0 + tw)) * NC + c0;
    u64 q0, q1, q2, q3;
    {
        ulonglong2 qA = *(const ulonglong2*)(g_q + qa);
        ulonglong2 qB = *(const ulonglong2*)(g_q + qa + 4);
        q0 = qA.x; q1 = qA.y; q2 = qB.x; q3 = qB.y;
    }

    const int sb = (td * 40 + th * 10 + tw) * 64 + l8 * 4;
    const int pbase = grp * 4 + hd;

    float lsum = 0.0f;
    {
        int n = 0;
#pragma unroll
        for (int di = 0; di < 3; di++) {
#pragma unroll
            for (int hi = 0; hi < 3; hi++) {
#pragma unroll
                for (int wi = 0; wi < 3; wi++) {
                    const int o = sb + (di * 40 + hi * 10 + wi) * 64;
                    ulonglong2 kA = *(const ulonglong2*)&hal[o];
                    ulonglong2 kB = *(const ulonglong2*)&hal[o + 32];
                    u64 t0 = fma2(q0, kA.x, 0ull);
                    u64 t1 = fma2(q1, kA.y, 0ull);
                    t0 = fma2(q2, kB.x, t0);
                    t1 = fma2(q3, kB.y, t1);
                    float2 df = unpack2(add2(t0, t1));
                    float sc = df.x + df.y;
                    sc += __shfl_xor_sync(0xffffffffu, sc, 1);  // head dot done
                    float p = ex2(sc);
                    lsum += p;
                    ps[n * 128 + pbase] = p;   // both pair-lanes store same value
                    n++;
                }
            }
        }
    }
    __syncthreads();   // all k reads + p writes done

    // ---- phase B: v-halo load over the same buffer ----
#pragma unroll
    for (int it = 0; it < 10; it++) {
        int e = tid + it * 256;
        int vox = e >> 4, f = e & 15;
        int slot = ((f & 1) << 3) | (f >> 1);
        int dd = vox / 40, rr2 = vox % 40, hh = rr2 / 10, ww = rr2 % 10;
        long g = gb + ((long)dd * PD2 + hh * PD + ww) * NC + f * 4;
        *(float4*)&hal[vox * 64 + slot * 4] = *(const float4*)&g_vp[g];
    }
    __syncthreads();

    u64 a0 = 0ull, a1 = 0ull, a2 = 0ull, a3 = 0ull;
    {
        int n = 0;
#pragma unroll
        for (int di = 0; di < 3; di++) {
#pragma unroll
            for (int hi = 0; hi < 3; hi++) {
#pragma unroll
                for (int wi = 0; wi < 3; wi++) {
                    const int o = sb + (di * 40 + hi * 10 + wi) * 64;
                    float p = ps[n * 128 + pbase];
                    u64 p2 = pack2(p, p);
                    ulonglong2 vA = *(const ulonglong2*)&hal[o];
                    ulonglong2 vB = *(const ulonglong2*)&hal[o + 32];
                    a0 = fma2(p2, vA.x, a0);
                    a1 = fma2(p2, vA.y, a1);
                    a2 = fma2(p2, vB.x, a2);
                    a3 = fma2(p2, vB.y, a3);
                    n++;
                }
            }
        }
    }

    const float inv = 1.0f / lsum;
    float2 r0 = unpack2(a0);
    float2 r1 = unpack2(a1);
    float2 r2 = unpack2(a2);
    float2 r3 = unpack2(a3);

    __syncthreads();   // all v/p reads done before hs overwrites

    hs[(c0 + 0) * 33 + grp] = r0.x * inv;
    hs[(c0 + 1) * 33 + grp] = r0.y * inv;
    hs[(c0 + 2) * 33 + grp] = r1.x * inv;
    hs[(c0 + 3) * 33 + grp] = r1.y * inv;
    hs[(c0 + 4) * 33 + grp] = r2.x * inv;
    hs[(c0 + 5) * 33 + grp] = r2.y * inv;
    hs[(c0 + 6) * 33 + grp] = r3.x * inv;
    hs[(c0 + 7) * 33 + grp] = r3.y * inv;
    __syncthreads();

    // channel-major output with residual add (32 vox x 64 ch)
#pragma unroll
    for (int k2 = 0; k2 < 8; k2++) {
        int idx = tid + k2 * 256;
        int c = idx >> 5, t = idx & 31;
        int ttd = t >> 4, tth = (t >> 3) & 1, ttw = t & 7;
        long gi = ((long)bb * NC + c) * NS + (d0 + ttd) * 576 + (h0 + tth) * 24 + (w0 + ttw);
        out[gi] = hs[c * 33 + t] + x[gi];
    }
}

// ---------------------------------------------------------------------------
extern "C" void kernel_launch(void* const* d_in, const int* in_sizes, int n_in,
                              void* d_out, int out_size)
{
    const float* x  = (const float*)d_in[0];
    // d_in[1] = cemb (unused by reference forward)
    const float* Wq = (const float*)d_in[2];
    const float* bq = (const float*)d_in[3];
    const float* Wk = (const float*)d_in[4];
    const float* bk = (const float*)d_in[5];
    const float* Wv = (const float*)d_in[6];
    const float* bv = (const float*)d_in[7];
    float* out = (float*)d_out;

    cudaFuncSetAttribute(k_attn, cudaFuncAttributeMaxDynamicSharedMemorySize, ATTN_SMEM);

    k_proj<<<NPROJ + NZERO, 256>>>(x, Wq, bq, Wk, bk, Wv, bv);
    k_attn<<<NB * 432, 256, ATTN_SMEM>>>(x, out);
}

// round 13
// speedup vs baseline: 1.1411x; 1.1411x over previous
#include <cuda_runtime.h>
#include <cstdint>

#define NS 13824            // D*H*W = 24*24*24
#define NB 2                // batch
#define NC 64               // channels
#define NVOX (NB * NS)      // 27648 voxels
#define PD 26               // padded dim
#define PD2 (PD * PD)       // 676
#define P3 (PD * PD * PD)   // 17576 padded voxels per batch
#define NBORD 3752          // border voxels per batch = P3 - NS
#define NPROJ (NVOX / 64)   // 432 projection blocks
#define NZERO ((NB * NBORD * 16) / 256)   // 469 border-zero blocks

// q unpadded voxel-major [n][c] (pre-scaled by 0.25*log2e);
// k,v zero-padded [b][dp][hp][wp][c]
__device__ float g_q [NVOX * NC];
__device__ float g_kp[NB * P3 * NC];
__device__ float g_vp[NB * P3 * NC];

typedef unsigned long long u64;

__device__ __forceinline__ u64 pack2(float lo, float hi) {
    u64 r; asm("mov.b64 %0,{%1,%2};" : "=l"(r) : "f"(lo), "f"(hi)); return r;
}
__device__ __forceinline__ float2 unpack2(u64 v) {
    float2 r; asm("mov.b64 {%0,%1},%2;" : "=f"(r.x), "=f"(r.y) : "l"(v)); return r;
}
__device__ __forceinline__ u64 fma2(u64 a, u64 b, u64 c) {
    u64 d; asm("fma.rn.f32x2 %0,%1,%2,%3;" : "=l"(d) : "l"(a), "l"(b), "l"(c)); return d;
}
__device__ __forceinline__ float ex2(float x) {
    float r; asm("ex2.approx.ftz.f32 %0,%1;" : "=f"(r) : "f"(x)); return r;
}

// ---------------------------------------------------------------------------
// Kernel 1: QKV projection + (tail blocks) border zeroing. (R6 kernel; q
// scale folds 0.25*log2e so attention uses raw EX2 — validated R10-R12.)
// ---------------------------------------------------------------------------
__global__ __launch_bounds__(256) void k_proj(
    const float* __restrict__ x,
    const float* __restrict__ Wq, const float* __restrict__ bq,
    const float* __restrict__ Wk, const float* __restrict__ bk,
    const float* __restrict__ Wv, const float* __restrict__ bv)
{
    __shared__ __align__(16) float WTs[64 * 68];   // WTs[j*68 + c] = W[c][j]
    __shared__ __align__(16) float Xs[64 * 64];    // Xs[j*64 + t]

    const int tid = threadIdx.x;

    if (blockIdx.x >= NPROJ) {
        // ---- border zeroing tail blocks ----
        int idx = (blockIdx.x - NPROJ) * 256 + tid;   // [0, NB*NBORD*16)
        int t  = idx >> 4;
        int c4 = (idx & 15) * 4;
        int bb = t / NBORD;
        int r  = t % NBORD;

        int dp, hp, wp;
        if (r < 1352) {                   // faces dp = 0 / 25
            dp = (r >= 676) ? 25 : 0;
            int q = (r >= 676) ? r - 676 : r;
            hp = q / PD; wp = q % PD;
        } else if (r < 2600) {            // faces hp = 0 / 25
            int q = r - 1352;
            dp = 1 + q / 52;
            int q2 = q % 52;
            hp = (q2 >= 26) ? 25 : 0;
            wp = (q2 >= 26) ? q2 - 26 : q2;
        } else {                          // faces wp = 0 / 25
            int q = r - 2600;
            dp = 1 + q / 48;
            int q2 = q % 48;
            hp = 1 + (q2 >> 1);
            wp = (q2 & 1) ? 25 : 0;
        }

        long vox = (long)bb * P3 + dp * PD2 + hp * PD + wp;
        float4 z = make_float4(0.f, 0.f, 0.f, 0.f);
        *(float4*)&g_kp[vox * NC + c4] = z;
        *(float4*)&g_vp[vox * NC + c4] = z;
        return;
    }

    // ---- projection blocks ----
    const int lane = tid & 31;
    const int wid  = tid >> 5;
    const int tile = blockIdx.x;               // 0..431
    const int bb   = tile / (NS / 64);
    const int s0   = (tile % (NS / 64)) * 64;

    const float* xb = x + (long)bb * NC * NS + s0;

#pragma unroll
    for (int k = 0; k < 16; k++) {
        int idx = tid + k * 256;
        int j = idx >> 6, u = idx & 63;
        Xs[j * 64 + u] = xb[(long)j * NS + u];
    }

    const int c0  = (wid & 1) * 32 + (lane >> 2) * 4;
    const int tv0 = (wid >> 1) * 16 + (lane & 3) * 4;

    const int sA = s0 + tv0;
    const int d  = sA / 576, h = (sA / 24) % 24, w0 = sA % 24;
    const long nq  = (long)(bb * NS + sA) * NC + c0;
    const long npk = ((long)bb * P3 + (d + 1) * PD2 + (h + 1) * PD + (w0 + 1)) * NC + c0;

    const float* Wsrc[3] = {Wq, Wk, Wv};
    const float* bsrc[3] = {bq, bk, bv};

#pragma unroll
    for (int m = 0; m < 3; m++) {
        __syncthreads();
        const float* W = Wsrc[m];
#pragma unroll
        for (int k2 = 0; k2 < 16; k2++) {
            int idx = tid + k2 * 256;
            int c = idx >> 6, j = idx & 63;
            WTs[j * 68 + c] = W[idx];
        }
        __syncthreads();

        const float4 bv4 = *(const float4*)&bsrc[m][c0];
        u64 acc[4][2];
#pragma unroll
        for (int t = 0; t < 4; t++) {
            acc[t][0] = pack2(bv4.x, bv4.y);
            acc[t][1] = pack2(bv4.z, bv4.w);
        }

#pragma unroll 8
        for (int j = 0; j < 64; j++) {
            ulonglong2 w = *(const ulonglong2*)&WTs[j * 68 + c0];
            float4 xv = *(const float4*)&Xs[j * 64 + tv0];
            u64 xd0 = pack2(xv.x, xv.x);
            u64 xd1 = pack2(xv.y, xv.y);
            u64 xd2 = pack2(xv.z, xv.z);
            u64 xd3 = pack2(xv.w, xv.w);
            acc[0][0] = fma2(w.x, xd0, acc[0][0]);
            acc[0][1] = fma2(w.y, xd0, acc[0][1]);
            acc[1][0] = fma2(w.x, xd1, acc[1][0]);
            acc[1][1] = fma2(w.y, xd1, acc[1][1]);
            acc[2][0] = fma2(w.x, xd2, acc[2][0]);
            acc[2][1] = fma2(w.y, xd2, acc[2][1]);
            acc[3][0] = fma2(w.x, xd3, acc[3][0]);
            acc[3][1] = fma2(w.y, xd3, acc[3][1]);
        }

        if (m == 0) {
            // 2^(q'.k) == e^(0.25 * q.k)
            const float qs = 0.25f * 1.4426950408889634f;
#pragma unroll
            for (int t = 0; t < 4; t++) {
                float2 a = unpack2(acc[t][0]);
                float2 b = unpack2(acc[t][1]);
                float4 o;
                o.x = a.x * qs; o.y = a.y * qs;
                o.z = b.x * qs; o.w = b.y * qs;
                *(float4*)&g_q[nq + (long)t * NC] = o;
            }
        } else {
            float* g = (m == 1) ? g_kp : g_vp;
#pragma unroll
            for (int t = 0; t < 4; t++) {
                float2 a = unpack2(acc[t][0]);
                float2 b = unpack2(acc[t][1]);
                float4 o; o.x = a.x; o.y = a.y; o.z = b.x; o.w = b.y;
                *(float4*)&g[npk + (long)t * NC] = o;
            }
        }
    }
}

// ---------------------------------------------------------------------------
// Kernel 2: 3x3x3 local attention + residual (R6 best-total attn, phased
// 4-query sliding window) with two mechanistic knobs:
//   - __launch_bounds__(256, 4): cap 64 regs -> 4 blocks/SM (was 80/3).
//   - raw EX2 (q pre-scaled by 0.25*log2e): deletes the FMUL before each
//     of the 108 MUFU.EX2 per thread.
// ---------------------------------------------------------------------------
__global__ __launch_bounds__(256, 4) void k_attn(
    const float* __restrict__ x, float* __restrict__ out)
{
    __shared__ float hs[64 * 65];

    const int tid  = threadIdx.x;
    const int lane = tid & 31;
    const int wid  = tid >> 5;

    const int n0 = blockIdx.x * 64;      // 64 voxels per block, same batch
    const int bb = n0 / NS;
    const int s0 = n0 % NS;

    const int half = lane >> 4;
    const int l4   = lane & 15;
    const int grp  = wid * 2 + half;     // query group 0..15
    const int sg   = s0 + grp * 4;       // first of 4 queries (w-aligned)
    const int d = sg / 576, h = (sg / 24) % 24, w0 = sg % 24;
    const int c0 = l4 * 4;               // quad (l4>>2) = head

    // q for the 4 queries
    u64 q01[4], q23[4];
    {
        const long qa = (long)(bb * NS + sg) * NC + c0;
#pragma unroll
        for (int i = 0; i < 4; i++) {
            ulonglong2 qv = *(const ulonglong2*)(g_q + qa + (long)i * NC);
            q01[i] = qv.x; q23[i] = qv.y;
        }
    }

    // padded base at (d+1, h+1, w0): row j covers padded w0+j; query i's
    // neighbors are rows j in {i, i+1, i+2}. Always in-range (padded).
    const long pb = ((long)bb * P3 + (d + 1) * PD2 + (h + 1) * PD + w0) * NC + c0;

    u64 acc01[4], acc23[4];
    float lsum[4];
#pragma unroll
    for (int i = 0; i < 4; i++) { acc01[i] = 0ull; acc23[i] = 0ull; lsum[i] = 0.0f; }

#pragma unroll
    for (int dh = 0; dh < 9; dh++) {
        const int di = dh / 3 - 1, hi = dh % 3 - 1;
        const long rb = pb + (long)(di * PD2 + hi * PD) * NC;
        const float* kb = g_kp + rb;
        const float* vb = g_vp + rb;

        // phase 1: batch all k-row loads, compute p for the 12 (i,j) pairs
        ulonglong2 kr[6];
#pragma unroll
        for (int j = 0; j < 6; j++) kr[j] = *(const ulonglong2*)(kb + j * NC);

        float pv[12];
        int pi = 0;
#pragma unroll
        for (int j = 0; j < 6; j++) {
            const int ilo = (j - 2 > 0) ? j - 2 : 0;
            const int ihi = (j < 3) ? j : 3;
#pragma unroll
            for (int i = ilo; i <= ihi; i++) {
                u64 dd = fma2(q01[i], kr[j].x, 0ull);
                dd = fma2(q23[i], kr[j].y, dd);
                float2 df = unpack2(dd);
                float sc = df.x + df.y;
                sc += __shfl_xor_sync(0xffffffffu, sc, 1);
                sc += __shfl_xor_sync(0xffffffffu, sc, 2);
                float p = ex2(sc);                // base-2 softmax (q pre-scaled)
                lsum[i] += p;
                pv[pi++] = p;
            }
        }

        // phase 2: batch all v-row loads, apply weights
        ulonglong2 vr[6];
#pragma unroll
        for (int j = 0; j < 6; j++) vr[j] = *(const ulonglong2*)(vb + j * NC);

        pi = 0;
#pragma unroll
        for (int j = 0; j < 6; j++) {
            const int ilo = (j - 2 > 0) ? j - 2 : 0;
            const int ihi = (j < 3) ? j : 3;
#pragma unroll
            for (int i = ilo; i <= ihi; i++) {
                u64 p2 = pack2(pv[pi], pv[pi]);
                pi++;
                acc01[i] = fma2(p2, vr[j].x, acc01[i]);
                acc23[i] = fma2(p2, vr[j].y, acc23[i]);
            }
        }
    }

#pragma unroll
    for (int i = 0; i < 4; i++) {
        const float inv = 1.0f / lsum[i];
        float2 a = unpack2(acc01[i]);
        float2 b = unpack2(acc23[i]);
        const int col = grp * 4 + i;
        hs[(c0 + 0) * 65 + col] = a.x * inv;
        hs[(c0 + 1) * 65 + col] = a.y * inv;
        hs[(c0 + 2) * 65 + col] = b.x * inv;
        hs[(c0 + 3) * 65 + col] = b.y * inv;
    }
    __syncthreads();

    // Coalesced channel-major output with residual add (64 vox x 64 ch)
#pragma unroll
    for (int k = 0; k < 16; k++) {
        int idx = tid + k * 256;
        int c = idx >> 6, t = idx & 63;
        long gi = ((long)bb * NC + c) * NS + s0 + t;
        out[gi] = hs[c * 65 + t] + x[gi];
    }
}

// ---------------------------------------------------------------------------
extern "C" void kernel_launch(void* const* d_in, const int* in_sizes, int n_in,
                              void* d_out, int out_size)
{
    const float* x  = (const float*)d_in[0];
    // d_in[1] = cemb (unused by reference forward)
    const float* Wq = (const float*)d_in[2];
    const float* bq = (const float*)d_in[3];
    const float* Wk = (const float*)d_in[4];
    const float* bk = (const float*)d_in[5];
    const float* Wv = (const float*)d_in[6];
    const float* bv = (const float*)d_in[7];
    float* out = (float*)d_out;

    k_proj<<<NPROJ + NZERO, 256>>>(x, Wq, bq, Wk, bk, Wv, bv);
    k_attn<<<NVOX / 64, 256>>>(x, out);
}